// round 13
// baseline (speedup 1.0000x reference)
#include <cuda_runtime.h>
#include <cstdint>

#define IMG_N  2048
#define OW     2044
#define OH     2044
#define TW     128
#define TH     8
#define IR     12          // TH + 4 input rows
#define IC     132         // TW + 4 input cols (floats per plane row)
#define NTH    256

// smem layout (bytes)
#define SX_OFF     0
#define SX_BYTES   (IR * IC * 4)              // 6336: raw int tile
#define PL_OFF     SX_BYTES                   // fp32 planes [IR][7][IC]
#define PL_BYTES   (IR * 7 * IC * 4)          // 44352
#define SMEM_BYTES (PL_OFF + PL_BYTES)        // 50688

typedef unsigned long long ull;
typedef unsigned int u32;

__constant__ float c_w[75];                   // weight[d][i][j] = d*25+i*5+j

__device__ __forceinline__ void fma2(ull& acc, ull a, ull b) {
    asm("fma.rn.f32x2 %0, %1, %2, %0;" : "+l"(acc) : "l"(a), "l"(b));
}
__device__ __forceinline__ ull dup2(float w) {
    ull r; asm("mov.b64 %0, {%1, %1};" : "=l"(r) : "f"(w)); return r;
}
__device__ __forceinline__ ull pack2(u32 lo, u32 hi) {
    ull r; asm("mov.b64 %0, {%1, %2};" : "=l"(r) : "r"(lo), "r"(hi)); return r;
}

// Expand np bit-planes [z0, z0+np) of the int tile into fp32 planes.
__device__ __forceinline__ void expand_planes(const int* __restrict__ sx,
                                              float* __restrict__ pl,
                                              int tid, int z0, int np)
{
    for (int idx = tid; idx < IR * IC; idx += NTH) {
        int rr = idx / IC, cc = idx - rr * IC;
        u32 v = (u32)sx[idx] >> z0;
        u32* dst = reinterpret_cast<u32*>(pl + (rr * 7) * IC + cc);
        #pragma unroll 7
        for (int p = 0; p < np; p++)
            dst[p * IC] = ((v >> p) & 1u) * 0x3F800000u;
    }
}

// One z-pass: NZ outputs, staged planes p in [0, NZ+2), 4 cols/thread (w-paired).
// Weights hoisted per-i from constant bank (uniform path, no RF pairs).
template<int NZ>
__device__ __forceinline__ void run_pass(const float* __restrict__ pl,
                                         int r, int col0, ull* accA, ull* accB)
{
    #pragma unroll
    for (int z = 0; z < NZ; z++) { accA[z] = 0ull; accB[z] = 0ull; }

    #pragma unroll 1
    for (int i = 0; i < 5; i++) {
        ull wv[15];
        #pragma unroll
        for (int d = 0; d < 3; d++)
            #pragma unroll
            for (int j = 0; j < 5; j++)
                wv[d * 5 + j] = dup2(c_w[d * 25 + i * 5 + j]);

        const float* rowi = pl + ((r + i) * 7) * IC + col0;

        #pragma unroll
        for (int kk = 0; kk < NZ + 2; kk++) {
            const ulonglong2* rk =
                reinterpret_cast<const ulonglong2*>(rowi + kk * IC);
            ulonglong2 qa = rk[0];   // {(v0,v1),(v2,v3)} — aligned pairs, free
            ulonglong2 qb = rk[1];   // {(v4,v5),(v6,v7)}

            ull S[7];
            S[0] = qa.x;  S[2] = qa.y;  S[4] = qb.x;  S[6] = qb.y;
            S[1] = pack2((u32)(qa.x >> 32), (u32)qa.y);   // (v1,v2)
            S[3] = pack2((u32)(qa.y >> 32), (u32)qb.x);   // (v3,v4)
            S[5] = pack2((u32)(qb.x >> 32), (u32)qb.y);   // (v5,v6)

            #pragma unroll
            for (int d = 0; d < 3; d++) {
                const int zz = kk - d;                 // compile-time per (kk,d)
                if (zz >= 0 && zz < NZ) {
                    #pragma unroll
                    for (int j = 0; j < 5; j++) {
                        const ull w = wv[d * 5 + j];
                        fma2(accA[zz], w, S[j]);       // cols (c, c+1)
                        fma2(accB[zz], w, S[j + 2]);   // cols (c+2, c+3)
                    }
                }
            }
        }
    }
}

template<int NZ>
__device__ __forceinline__ void store_pass(float* __restrict__ out, int h, int w,
                                           int z0, float bv,
                                           const ull* accA, const ull* accB)
{
    if (h >= OH || w >= OW) return;
    const bool full = (w + 4 <= OW);
    #pragma unroll
    for (int zz = 0; zz < NZ; zz++) {
        float2 a = *reinterpret_cast<const float2*>(&accA[zz]);
        float2 b = *reinterpret_cast<const float2*>(&accB[zz]);
        size_t off = ((size_t)(z0 + zz) * OH + h) * OW + w;
        if (full) {
            *reinterpret_cast<float4*>(out + off) =
                make_float4(a.x + bv, a.y + bv, b.x + bv, b.y + bv);
        } else {
            float vals[4] = { a.x + bv, a.y + bv, b.x + bv, b.y + bv };
            #pragma unroll
            for (int c = 0; c < 4; c++)
                if (w + c < OW) out[off + c] = vals[c];
        }
    }
}

__global__ void __launch_bounds__(NTH, 4)
conv2dto3d_kernel(const int* __restrict__ x,
                  const float* __restrict__ bias,
                  float* __restrict__ out)
{
    extern __shared__ unsigned char smem[];
    int*   sx = reinterpret_cast<int*>(smem + SX_OFF);
    float* pl = reinterpret_cast<float*>(smem + PL_OFF);

    const int tid   = threadIdx.x;
    const int wbase = blockIdx.x * TW;
    const int hbase = blockIdx.y * TH;

    // ---- load int tile (clamped) ----
    for (int idx = tid; idx < IR * IC; idx += NTH) {
        int rr = idx / IC, cc = idx - rr * IC;
        int ri = hbase + rr; if (ri > IMG_N - 1) ri = IMG_N - 1;
        int ci = wbase + cc; if (ci > IMG_N - 1) ci = IMG_N - 1;
        sx[idx] = x[ri * IMG_N + ci];
    }
    __syncthreads();

    const int g = tid & 31;          // 32 column groups of 4
    const int r = tid >> 5;          // local row 0..7
    const int col0 = g * 4;
    const int h = hbase + r;
    const int w = wbase + col0;
    const float bv = bias[0];

    ull accA[5], accB[5];

    // ---- pass 0: z in [0..4], planes 0..6 ----
    expand_planes(sx, pl, tid, 0, 7);
    __syncthreads();
    run_pass<5>(pl, r, col0, accA, accB);
    __syncthreads();
    store_pass<5>(out, h, w, 0, bv, accA, accB);

    // ---- pass 1: z in [5..9], planes 5..11 ----
    expand_planes(sx, pl, tid, 5, 7);
    __syncthreads();
    run_pass<5>(pl, r, col0, accA, accB);
    __syncthreads();
    store_pass<5>(out, h, w, 5, bv, accA, accB);

    // ---- pass 2: z in [10..13], planes 10..15 ----
    expand_planes(sx, pl, tid, 10, 6);
    __syncthreads();
    run_pass<4>(pl, r, col0, accA, accB);
    store_pass<4>(out, h, w, 10, bv, accA, accB);
}

extern "C" void kernel_launch(void* const* d_in, const int* in_sizes, int n_in,
                              void* d_out, int out_size)
{
    const int*   x      = (const int*)d_in[0];
    const float* weight = (const float*)d_in[1];
    const float* bias   = (const float*)d_in[2];
    float*       out    = (float*)d_out;

    cudaMemcpyToSymbolAsync(c_w, weight, 75 * sizeof(float), 0,
                            cudaMemcpyDeviceToDevice, 0);

    cudaFuncSetAttribute(conv2dto3d_kernel,
                         cudaFuncAttributeMaxDynamicSharedMemorySize, SMEM_BYTES);

    dim3 grid((OW + TW - 1) / TW, (OH + TH - 1) / TH);   // 16 x 256
    conv2dto3d_kernel<<<grid, NTH, SMEM_BYTES>>>(x, bias, out);
}